// round 10
// baseline (speedup 1.0000x reference)
#include <cuda_runtime.h>
#include <cuda_bf16.h>
#include <cstdint>

// WaveletPreprocessing: level-1 orthonormal Haar wavedec2 + waverec2 is an
// exact identity -> pure 512 MiB HBM->HBM copy.
//
// Search history:
//   R1 plain float4 grid-stride:         178.9us (DRAM 74.2%)
//   R2 __ldcs/__stcs, 512T x  8 float4:  164.4us (DRAM 84.3%)
//   R3 persistent grid:                  181.0us
//   R4 copy-engine memcpyAsync:          344.2us
//   R5 __stwt stores:                    168.0us
//   R7 256T x 16 float4 (regs=72):       156.1us (DRAM 85.7%)  <- best
//   R8 128T x 32 float4 (regs=138):      156.0us (neutral: depth axis saturated)
// R9: overlap read & write phases within a warp. 3-stage pipeline per block:
//   load A[16]  ->  (store A[k] || load B[k]) interleaved  ->  store B[16].
// Keeps read requests streaming while stores drain, smoothing the
// read/write mix at the DRAM controller (the turnaround is what caps us
// at ~85%). Depth per stage = 16 (R7's sweet spot).

constexpr int DEPTH   = 16;                    // float4 per stage
constexpr int THREADS = 256;
constexpr int TILE    = THREADS * DEPTH * 2;   // 8192 float4 = 128 KiB / block

__global__ void __launch_bounds__(THREADS, 2)
haar_identity_copy_kernel(const float4* __restrict__ src,
                          float4* __restrict__ dst,
                          long long n_vec)
{
    long long base = (long long)blockIdx.x * TILE + threadIdx.x;

    if (base + (long long)(2 * DEPTH - 1) * THREADS < n_vec) {
        float4 a[DEPTH], b[DEPTH];

        // Stage 1: front-batch 16 loads (batch A).
#pragma unroll
        for (int k = 0; k < DEPTH; k++)
            a[k] = __ldcs(&src[base + (long long)k * THREADS]);

        // Stage 2: interleave — issue batch-B load, then batch-A store.
        // Reads keep flowing into the DRAM scheduler while A drains.
#pragma unroll
        for (int k = 0; k < DEPTH; k++) {
            b[k] = __ldcs(&src[base + (long long)(DEPTH + k) * THREADS]);
            __stcs(&dst[base + (long long)k * THREADS], a[k]);
        }

        // Stage 3: drain batch B.
#pragma unroll
        for (int k = 0; k < DEPTH; k++)
            __stcs(&dst[base + (long long)(DEPTH + k) * THREADS], b[k]);
    } else {
        // Tail tile (never taken for n_vec = 2^25, kept for shape-safety).
#pragma unroll
        for (int k = 0; k < 2 * DEPTH; k++) {
            long long idx = base + (long long)k * THREADS;
            if (idx < n_vec) __stcs(&dst[idx], __ldcs(&src[idx]));
        }
    }
}

extern "C" void kernel_launch(void* const* d_in, const int* in_sizes, int n_in,
                              void* d_out, int out_size)
{
    const float* x = (const float*)d_in[0];
    float* out = (float*)d_out;

    long long n = (long long)in_sizes[0];   // 134,217,728 floats
    long long n_vec = n / 4;                // 33,554,432 float4 (exact)

    int blocks = (int)((n_vec + TILE - 1) / TILE);  // 4096 blocks

    haar_identity_copy_kernel<<<blocks, THREADS>>>(
        (const float4*)x, (float4*)out, n_vec);

    (void)n_in; (void)out_size;
}

// round 11
// speedup vs baseline: 1.0102x; 1.0102x over previous
#include <cuda_runtime.h>
#include <cuda_bf16.h>
#include <cstdint>

// WaveletPreprocessing: level-1 orthonormal Haar wavedec2 + waverec2 is an
// exact identity (perfect reconstruction, even dims, crop is a no-op) ->
// the task is a pure 512 MiB HBM->HBM copy (output bytes == input bytes,
// so a copy is the information-theoretic optimum).
//
// Final configuration after 10-round search:
//   R1 plain float4 grid-stride:         178.9us (DRAM 74.2%)
//   R2 __ldcs/__stcs, 512T x  8 float4:  164.4us (DRAM 84.3%)
//   R3 persistent grid:                  181.0us (lost cross-CTA overlap)
//   R4 copy-engine memcpyAsync:          344.2us (CE ~3.1 TB/s)
//   R5 __stwt stores:                    168.0us (loses LTS victim bursting)
//   R7 256T x 16 float4 (regs=72):       156.1us (DRAM 85.7%)  <- FINAL
//   R8 128T x 32 float4:                 156.0us (tied; depth axis saturated)
//   R9 interleaved ld/st phases:         158.0us (mix already blended across SMs)
// ~6.8 TB/s = 85% of spec is the measured 1:1-stream wall on this part
// (read/write turnaround bound; LTS cap is path-independent, TMA == LDG).

constexpr int UNROLL  = 16;
constexpr int THREADS = 256;

__global__ void __launch_bounds__(THREADS, 2)
haar_identity_copy_kernel(const float4* __restrict__ src,
                          float4* __restrict__ dst,
                          long long n_vec)
{
    // One 64 KiB tile (THREADS*UNROLL float4) per block; one-shot grid.
    // Fresh blocks' front-batched loads overlap retiring blocks' store
    // drains across tile boundaries.
    long long base = (long long)blockIdx.x * (THREADS * UNROLL) + threadIdx.x;

    if (base + (long long)(UNROLL - 1) * THREADS < n_vec) {
        // 16 genuinely-outstanding coalesced evict-first LDG.128 per thread
        // (regs~72 forces a real 16-deep scoreboard window, the measured
        // sweet spot), then 16 evict-first STG.128.
        float4 v[UNROLL];
#pragma unroll
        for (int k = 0; k < UNROLL; k++)
            v[k] = __ldcs(&src[base + (long long)k * THREADS]);
#pragma unroll
        for (int k = 0; k < UNROLL; k++)
            __stcs(&dst[base + (long long)k * THREADS], v[k]);
    } else {
        // Tail tile (never taken for n_vec = 2^25, kept for shape-safety).
#pragma unroll
        for (int k = 0; k < UNROLL; k++) {
            long long idx = base + (long long)k * THREADS;
            if (idx < n_vec) __stcs(&dst[idx], __ldcs(&src[idx]));
        }
    }
}

extern "C" void kernel_launch(void* const* d_in, const int* in_sizes, int n_in,
                              void* d_out, int out_size)
{
    const float* x = (const float*)d_in[0];
    float* out = (float*)d_out;

    long long n = (long long)in_sizes[0];   // 134,217,728 floats
    long long n_vec = n / 4;                // 33,554,432 float4 (exact)

    long long tile = (long long)THREADS * UNROLL;   // 4096 float4 / block
    int blocks = (int)((n_vec + tile - 1) / tile);  // 8192 blocks

    haar_identity_copy_kernel<<<blocks, THREADS>>>(
        (const float4*)x, (float4*)out, n_vec);

    (void)n_in; (void)out_size;
}